// round 10
// baseline (speedup 1.0000x reference)
#include <cuda_runtime.h>
#include <cuda_bf16.h>
#include <math.h>
#include <stdint.h>

#define BATCH 4
#define SEQ 4096
#define NH 16
#define HD 64
#define DIM 1024
#define BH (BATCH*NH)          // 64
#define CHUNK 64
#define NCHUNK (SEQ/CHUNK)     // 64
#define MTOT (BATCH*SEQ)       // 16384
#define FSCALE 0.35355339059327373f   // 64^-0.25

// ================= helpers =================
__device__ __forceinline__ uint32_t smem_u32(const void* p) {
    uint32_t a;
    asm("{ .reg .u64 t; cvta.to.shared.u64 t, %1; cvt.u32.u64 %0, t; }" : "=r"(a) : "l"(p));
    return a;
}
#define SW128(off) ((off) ^ (((off) >> 3) & 0x70))

__device__ __forceinline__ void cp16(uint32_t sa, const void* g) {
    asm volatile("cp.async.cg.shared.global [%0], [%1], 16;\n" :: "r"(sa), "l"(g) : "memory");
}
#define CP_COMMIT()  asm volatile("cp.async.commit_group;\n" ::: "memory")
#define CP_WAIT(n)   asm volatile("cp.async.wait_group %0;\n" :: "n"(n) : "memory")

__device__ __forceinline__ void ldsm4(uint32_t* r, uint32_t addr) {
    asm volatile("ldmatrix.sync.aligned.m8n8.x4.shared.b16 {%0,%1,%2,%3}, [%4];"
        : "=r"(r[0]), "=r"(r[1]), "=r"(r[2]), "=r"(r[3]) : "r"(addr));
}
__device__ __forceinline__ void ldsm4t(uint32_t* r, uint32_t addr) {
    asm volatile("ldmatrix.sync.aligned.m8n8.x4.trans.shared.b16 {%0,%1,%2,%3}, [%4];"
        : "=r"(r[0]), "=r"(r[1]), "=r"(r[2]), "=r"(r[3]) : "r"(addr));
}
__device__ __forceinline__ void mma_bf16(float* c, const uint32_t* a, const uint32_t* b) {
    asm volatile(
        "mma.sync.aligned.m16n8k16.row.col.f32.bf16.bf16.f32 "
        "{%0,%1,%2,%3}, {%4,%5,%6,%7}, {%8,%9}, {%0,%1,%2,%3};"
        : "+f"(c[0]), "+f"(c[1]), "+f"(c[2]), "+f"(c[3])
        : "r"(a[0]), "r"(a[1]), "r"(a[2]), "r"(a[3]), "r"(b[0]), "r"(b[1]));
}
// pack two fp32 -> bf16x2 (lo in low half)
__device__ __forceinline__ uint32_t pack_bf16(float lo, float hi) {
    uint32_t r;
    asm("cvt.rn.bf16x2.f32 %0, %1, %2;" : "=r"(r) : "f"(hi), "f"(lo));
    return r;
}

// ================= scratch =================
__device__ float g_qf  [ (size_t)BH * SEQ * HD ];
__device__ float g_kf  [ (size_t)BH * SEQ * HD ];
__device__ float g_vf  [ (size_t)BH * SEQ * HD ];
__device__ float g_Skv [ (size_t)BH * NCHUNK * HD * HD ];
__device__ float g_Pkv [ (size_t)BH * NCHUNK * HD * HD ];
__device__ float g_Sks [ (size_t)BH * NCHUNK * HD ];
__device__ float g_Pks [ (size_t)BH * NCHUNK * HD ];
__device__ float g_cos [ (size_t)SEQ * 32 ];
__device__ float g_sin [ (size_t)SEQ * 32 ];
__device__ __nv_bfloat16 g_xhi [ (size_t)MTOT * DIM ];
__device__ __nv_bfloat16 g_xlo [ (size_t)MTOT * DIM ];
__device__ __nv_bfloat16 g_wqhi[ (size_t)3 * DIM * DIM ];
__device__ __nv_bfloat16 g_wqlo[ (size_t)3 * DIM * DIM ];
__device__ __nv_bfloat16 g_wohi[ (size_t)DIM * DIM ];
__device__ __nv_bfloat16 g_wolo[ (size_t)DIM * DIM ];
__device__ __nv_bfloat16 g_ahi [ (size_t)MTOT * DIM ];
__device__ __nv_bfloat16 g_alo [ (size_t)MTOT * DIM ];

// ================= rope table =================
__global__ __launch_bounds__(256) void rope_init()
{
    int idx = blockIdx.x * 256 + threadIdx.x;
    int j = idx & 31, t = idx >> 5;
    float inv = expf(-0.28782313662425572f * (float)j);
    float s, c;
    sincosf((float)t * inv, &s, &c);
    g_cos[idx] = c; g_sin[idx] = s;
}

// ================= split kernels =================
__global__ __launch_bounds__(256) void split_kernel(const float* __restrict__ in,
                                                    __nv_bfloat16* __restrict__ hi,
                                                    __nv_bfloat16* __restrict__ lo)
{
    size_t i = ((size_t)blockIdx.x * 256 + threadIdx.x) * 4;
    float4 v = *(const float4*)(in + i);
    float a[4] = {v.x, v.y, v.z, v.w};
    __nv_bfloat16 h[4], l[4];
#pragma unroll
    for (int j = 0; j < 4; j++) {
        h[j] = __float2bfloat16(a[j]);
        l[j] = __float2bfloat16(a[j] - __bfloat162float(h[j]));
    }
    *(uint2*)(hi + i) = *(uint2*)h;
    *(uint2*)(lo + i) = *(uint2*)l;
}

__global__ __launch_bounds__(256) void tsplit_kernel(const float* __restrict__ W,
                                                     __nv_bfloat16* __restrict__ hi,
                                                     __nv_bfloat16* __restrict__ lo,
                                                     int K, int N)
{
    __shared__ float t[32][33];
    int n0 = blockIdx.x * 32, k0 = blockIdx.y * 32;
    int tx = threadIdx.x, ty = threadIdx.y;
#pragma unroll
    for (int i = 0; i < 4; i++)
        t[ty + i * 8][tx] = W[(size_t)(k0 + ty + i * 8) * N + n0 + tx];
    __syncthreads();
#pragma unroll
    for (int i = 0; i < 4; i++) {
        float v = t[tx][ty + i * 8];
        __nv_bfloat16 h = __float2bfloat16(v);
        __nv_bfloat16 l = __float2bfloat16(v - __bfloat162float(h));
        size_t o = (size_t)(n0 + ty + i * 8) * K + k0 + tx;
        hi[o] = h; lo[o] = l;
    }
}

// ================= mma.sync bf16x3 GEMM (KC=32, 3 stages, 2 CTAs/SM) ==========
#define STAGE_BYTES 32768
#define NSTAGE 3
#define GEMM_SMEM (NSTAGE * STAGE_BYTES)
#define OFF_B 16384
#define KCH 32
#define NCH (1024 / KCH)

__device__ __forceinline__ void load_chunk(uint32_t stg,
    const __nv_bfloat16* __restrict__ Ahi, const __nv_bfloat16* __restrict__ Alo,
    const __nv_bfloat16* __restrict__ Bhi, const __nv_bfloat16* __restrict__ Blo,
    int m0, int n0, int k0, int tid)
{
#pragma unroll
    for (int i = 0; i < 8; i++) {
        int idx = tid + i * 256;
        int tile = idx >> 10;
        int rem = idx & 1023;
        int row = rem >> 3, cv = rem & 7;
        uint32_t dst = stg + tile * OFF_B + SW128((uint32_t)(row * 128 + cv * 16));
        const __nv_bfloat16* base;
        int kk = k0 + (cv & 3) * 8;
        if (tile == 0) base = (cv < 4) ? Ahi : Alo;
        else           base = (cv < 4) ? Bhi : Blo;
        int grow = (tile == 0) ? (m0 + row) : (n0 + row);
        cp16(dst, base + (size_t)grow * 1024 + kk);
    }
}

template <int MODE>
__global__ __launch_bounds__(256, 2) void gemm_tc(
    const __nv_bfloat16* __restrict__ Ahi, const __nv_bfloat16* __restrict__ Alo,
    const __nv_bfloat16* __restrict__ Bhi, const __nv_bfloat16* __restrict__ Blo,
    float* __restrict__ C, int Ncols)
{
    extern __shared__ __align__(16) char smem[];
    const uint32_t sb = smem_u32(smem);
    const int tid = threadIdx.x;
    const int lane = tid & 31, wid = tid >> 5;
    const int wm = (wid & 1) * 64;
    const int wn = (wid >> 1) * 32;
    const int m0 = blockIdx.y * 128;
    const int n0 = blockIdx.x * 128;

    float acc[4][4][4];
#pragma unroll
    for (int i = 0; i < 4; i++)
#pragma unroll
        for (int j = 0; j < 4; j++)
#pragma unroll
            for (int r = 0; r < 4; r++) acc[i][j][r] = 0.f;

    const int la_r = lane & 15;
    const int la_h = lane >> 4;
    const int lb_row = ((lane >> 4) & 1) * 8 + (lane & 7);
    const int lb_k = (lane >> 3) & 1;

    load_chunk(sb,                   Ahi, Alo, Bhi, Blo, m0, n0, 0,        tid); CP_COMMIT();
    load_chunk(sb + STAGE_BYTES,     Ahi, Alo, Bhi, Blo, m0, n0, KCH,      tid); CP_COMMIT();
    load_chunk(sb + 2 * STAGE_BYTES, Ahi, Alo, Bhi, Blo, m0, n0, 2 * KCH,  tid); CP_COMMIT();

    int stage = 0;
    for (int c = 0; c < NCH; c++) {
        if (c <= NCH - 3)      { CP_WAIT(2); }
        else if (c == NCH - 2) { CP_WAIT(1); }
        else                   { CP_WAIT(0); }
        __syncthreads();

        const uint32_t stg = sb + stage * STAGE_BYTES;
#pragma unroll
        for (int ks = 0; ks < 2; ks++) {
            const int kb = ks * 32 + la_h * 16;
            uint32_t ahi[4][4], alo[4][4];
#pragma unroll
            for (int mt = 0; mt < 4; mt++) {
                uint32_t ro = (uint32_t)((wm + mt * 16 + la_r) * 128);
                ldsm4(ahi[mt], stg + SW128(ro + kb));
                ldsm4(alo[mt], stg + SW128(ro + kb + 64));
            }
            const int kbb = ks * 32 + lb_k * 16;
#pragma unroll
            for (int ntp = 0; ntp < 2; ntp++) {
                uint32_t bh[4], bl[4];
                uint32_t ro = (uint32_t)((wn + ntp * 16 + lb_row) * 128);
                ldsm4(bh, stg + OFF_B + SW128(ro + kbb));
                ldsm4(bl, stg + OFF_B + SW128(ro + kbb + 64));
#pragma unroll
                for (int mt = 0; mt < 4; mt++) {
                    mma_bf16(acc[mt][2 * ntp],     ahi[mt], bh);
                    mma_bf16(acc[mt][2 * ntp],     ahi[mt], bl);
                    mma_bf16(acc[mt][2 * ntp],     alo[mt], bh);
                    mma_bf16(acc[mt][2 * ntp + 1], ahi[mt], bh + 2);
                    mma_bf16(acc[mt][2 * ntp + 1], ahi[mt], bl + 2);
                    mma_bf16(acc[mt][2 * ntp + 1], alo[mt], bh + 2);
                }
            }
        }
        __syncthreads();
        if (c + 3 < NCH) {
            load_chunk(sb + stage * STAGE_BYTES, Ahi, Alo, Bhi, Blo, m0, n0, (c + 3) * KCH, tid);
            CP_COMMIT();
        }
        stage = (stage + 1 == NSTAGE) ? 0 : stage + 1;
    }

    const int rquad = lane >> 2, cpair = (lane & 3) * 2;

    if (MODE == 0) {
#pragma unroll
        for (int mt = 0; mt < 4; mt++) {
#pragma unroll
            for (int nt = 0; nt < 4; nt++) {
                int row = m0 + wm + mt * 16 + rquad;
                int col = n0 + wn + nt * 8 + cpair;
                float2* p0 = (float2*)(C + (size_t)row * Ncols + col);
                float2* p1 = (float2*)(C + (size_t)(row + 8) * Ncols + col);
                *p0 = make_float2(acc[mt][nt][0], acc[mt][nt][1]);
                *p1 = make_float2(acc[mt][nt][2], acc[mt][nt][3]);
            }
        }
    } else {
        float* ct = (float*)smem;
#pragma unroll
        for (int mt = 0; mt < 4; mt++) {
#pragma unroll
            for (int nt = 0; nt < 4; nt++) {
                int row = wm + mt * 16 + rquad;
                int col = wn + nt * 8 + cpair;
                *(float2*)&ct[row * 128 + col]       = make_float2(acc[mt][nt][0], acc[mt][nt][1]);
                *(float2*)&ct[(row + 8) * 128 + col] = make_float2(acc[mt][nt][2], acc[mt][nt][3]);
            }
        }
        __syncthreads();

        const int region = n0 >> 10;
        const int h0 = (n0 & 1023) >> 6;

        if (region < 2) {
            float* dst = (region == 0) ? g_qf : g_kf;
#pragma unroll 4
            for (int i = 0; i < 32; i++) {
                int p = i * 256 + tid;
                int row = p >> 6;
                int w = p & 63;
                int hh = w >> 5;
                int j = w & 31;
                float x1 = ct[row * 128 + hh * 64 + j];
                float x2 = ct[row * 128 + hh * 64 + j + 32];
                int gm = m0 + row;
                int t = gm & 4095, b = gm >> 12;
                float cc = g_cos[t * 32 + j];
                float s  = g_sin[t * 32 + j];
                float a1 = (x1 * cc - x2 * s) * FSCALE;
                float a2 = (x1 * s + x2 * cc) * FSCALE;
                a1 = (a1 > 0.f) ? a1 + 1.f : __expf(a1);
                a2 = (a2 > 0.f) ? a2 + 1.f : __expf(a2);
                size_t o = ((size_t)(b * NH + h0 + hh) * SEQ + t) * 64 + j;
                dst[o] = a1; dst[o + 32] = a2;
            }
        } else {
#pragma unroll 4
            for (int i = 0; i < 64; i++) {
                int p = i * 256 + tid;
                int row = p >> 7, col = p & 127;
                int gm = m0 + row;
                int t = gm & 4095, b = gm >> 12;
                size_t o = ((size_t)(b * NH + h0 + (col >> 6)) * SEQ + t) * 64 + (col & 63);
                g_vf[o] = ct[row * 128 + col];
            }
        }
    }
}

// ================= per-chunk local sums =================
__global__ __launch_bounds__(256) void chunksum_kernel()
{
    const int c = blockIdx.x, bh = blockIdx.y;
    const int tid = threadIdx.x;
    __shared__ __align__(16) float ks[CHUNK][HD];
    __shared__ __align__(16) float vs[CHUNK][HD];

    const float* Kg = g_kf + ((size_t)bh * SEQ + c * CHUNK) * HD;
    const float* Vg = g_vf + ((size_t)bh * SEQ + c * CHUNK) * HD;

    const int row = tid >> 2, f0 = tid & 3;
#pragma unroll
    for (int i = 0; i < 4; i++) {
        int f = (f0 + i * 4) * 4;
        *(float4*)&ks[row][f] = *(const float4*)(Kg + row * 64 + f);
        *(float4*)&vs[row][f] = *(const float4*)(Vg + row * 64 + f);
    }
    __syncthreads();

    const int m = tid & 63;
    const int dbase = (tid >> 6) * 16;
    float acc[16];
#pragma unroll
    for (int i = 0; i < 16; i++) acc[i] = 0.f;

    for (int t = 0; t < CHUNK; t++) {
        float v = vs[t][m];
#pragma unroll
        for (int w = 0; w < 4; w++) {
            float4 kk = *(float4*)&ks[t][dbase + w * 4];
            acc[w * 4 + 0] += kk.x * v;
            acc[w * 4 + 1] += kk.y * v;
            acc[w * 4 + 2] += kk.z * v;
            acc[w * 4 + 3] += kk.w * v;
        }
    }

    float* S = g_Skv + ((size_t)bh * NCHUNK + c) * (HD * HD);
#pragma unroll
    for (int d = 0; d < 16; d++)
        S[(dbase + d) * 64 + m] = acc[d];

    if (tid < 64) {
        float s = 0.f;
        for (int t = 0; t < CHUNK; t++) s += ks[t][tid];
        g_Sks[((size_t)bh * NCHUNK + c) * HD + tid] = s;
    }
}

// ================= exclusive prefixes =================
__global__ __launch_bounds__(256) void prefix_kernel()
{
    int e = blockIdx.x * 256 + threadIdx.x;
    int bh = e >> 12, el = e & 4095;
    float run = 0.f;
    for (int c = 0; c < NCHUNK; c++) {
        size_t i = ((size_t)bh * NCHUNK + c) * (HD * HD) + el;
        g_Pkv[i] = run;
        run += g_Skv[i];
    }
}
__global__ __launch_bounds__(256) void prefix_ks_kernel()
{
    int e = blockIdx.x * 256 + threadIdx.x;
    int bh = e >> 6, d = e & 63;
    float run = 0.f;
    for (int c = 0; c < NCHUNK; c++) {
        size_t i = ((size_t)bh * NCHUNK + c) * HD + d;
        g_Pks[i] = run;
        run += g_Sks[i];
    }
}

// ================= tensor-core chunk attention =================
// 128 threads, 4 warps x 16 rows. bf16x3 mma for QK^T, S.V, Q.Pkv.
// smem: 8 bf16 tiles [64][64] (8KB each, SW128) + dinv[64].
#define AT_QHI 0
#define AT_QLO 8192
#define AT_KHI 16384
#define AT_KLO 24576
#define AT_VHI 32768
#define AT_VLO 40960
#define AT_PHI 49152
#define AT_PLO 57344
#define AT_DINV 65536
#define ATTN_SMEM (65536 + 256)

__global__ __launch_bounds__(128, 2) void attn_kernel()
{
    const int c = blockIdx.x, bh = blockIdx.y;
    const int tid = threadIdx.x;
    const int lane = tid & 31, wid = tid >> 5;
    extern __shared__ __align__(16) char smem[];
    const uint32_t sb = smem_u32(smem);
    float* dinv_s = (float*)(smem + AT_DINV);

    const int t0 = c * CHUNK;
    const size_t fbase = ((size_t)bh * SEQ + t0) * HD;
    const size_t pbase = ((size_t)bh * NCHUNK + c) * (HD * HD);

    // ---- conversion pass: each warp converts one tile (Q,K,V,P) to bf16 hi/lo
    {
        const float* src;
        int hioff;
        if      (wid == 0) { src = g_qf + fbase;  hioff = AT_QHI; }
        else if (wid == 1) { src = g_kf + fbase;  hioff = AT_KHI; }
        else if (wid == 2) { src = g_vf + fbase;  hioff = AT_VHI; }
        else               { src = g_Pkv + pbase; hioff = AT_PHI; }
        const int cl = (lane & 15) * 4;           // col base (elems)
        const int rh = lane >> 4;                 // row half
#pragma unroll
        for (int i = 0; i < 32; i++) {
            int row = i * 2 + rh;
            float4 v = *(const float4*)(src + row * 64 + cl);
            uint32_t h0 = pack_bf16(v.x, v.y);
            uint32_t h1 = pack_bf16(v.z, v.w);
            float r0 = v.x - __uint_as_float(h0 << 16);
            float r1 = v.y - __uint_as_float(h0 & 0xffff0000u);
            float r2 = v.z - __uint_as_float(h1 << 16);
            float r3 = v.w - __uint_as_float(h1 & 0xffff0000u);
            uint32_t l0 = pack_bf16(r0, r1);
            uint32_t l1 = pack_bf16(r2, r3);
            uint32_t ad = SW128((uint32_t)(row * 128 + cl * 2));
            *(uint2*)(smem + hioff + ad)        = make_uint2(h0, h1);
            *(uint2*)(smem + hioff + 8192 + ad) = make_uint2(l0, l1);
        }
    }
    __syncthreads();

    const int wm = wid * 16;
    const int la_r = lane & 15, la_h = lane >> 4;
    const int lb_row = ((lane >> 4) & 1) * 8 + (lane & 7);
    const int lb_k = (lane >> 3) & 1;
    const int tj_j = lane & 7, tj_sel = lane >> 3;   // trans-B lane mapping

    // ---- Phase A: S = Q K^T (bf16x3)
    float s[8][4];
#pragma unroll
    for (int i = 0; i < 8; i++)
#pragma unroll
        for (int r = 0; r < 4; r++) s[i][r] = 0.f;

#pragma unroll
    for (int kt = 0; kt < 4; kt++) {
        uint32_t ah[4], al[4];
        uint32_t ao = SW128((uint32_t)((wm + la_r) * 128 + kt * 32 + la_h * 16));
        ldsm4(ah, sb + AT_QHI + ao);
        ldsm4(al, sb + AT_QLO + ao);
#pragma unroll
        for (int np = 0; np < 4; np++) {
            uint32_t bhh[4], bll[4];
            uint32_t bo = SW128((uint32_t)((np * 16 + lb_row) * 128 + kt * 32 + lb_k * 16));
            ldsm4(bhh, sb + AT_KHI + bo);
            ldsm4(bll, sb + AT_KLO + bo);
            mma_bf16(s[2 * np],     ah, bhh);
            mma_bf16(s[2 * np],     ah, bll);
            mma_bf16(s[2 * np],     al, bhh);
            mma_bf16(s[2 * np + 1], ah, bhh + 2);
            mma_bf16(s[2 * np + 1], ah, bll + 2);
            mma_bf16(s[2 * np + 1], al, bhh + 2);
        }
    }

    // ---- mask + rowsums
    const int r0 = wm + (lane >> 2), r1 = r0 + 8;
    float rs0 = 0.f, rs1 = 0.f;
#pragma unroll
    for (int nt = 0; nt < 8; nt++) {
        int c0 = nt * 8 + (lane & 3) * 2;
        if (c0 > r0)     s[nt][0] = 0.f;
        if (c0 + 1 > r0) s[nt][1] = 0.f;
        if (c0 > r1)     s[nt][2] = 0.f;
        if (c0 + 1 > r1) s[nt][3] = 0.f;
        rs0 += s[nt][0] + s[nt][1];
        rs1 += s[nt][2] + s[nt][3];
    }
    rs0 += __shfl_xor_sync(0xffffffffu, rs0, 1);
    rs0 += __shfl_xor_sync(0xffffffffu, rs0, 2);
    rs1 += __shfl_xor_sync(0xffffffffu, rs1, 1);
    rs1 += __shfl_xor_sync(0xffffffffu, rs1, 2);
    if ((lane & 3) == 0) { dinv_s[r0] = rs0; dinv_s[r1] = rs1; }
    __syncthreads();

    if (tid < 64) {
        const float* qrow = g_qf + fbase + tid * 64;
        const float* pks  = g_Pks + ((size_t)bh * NCHUNK + c) * HD;
        float sum = dinv_s[tid];
#pragma unroll
        for (int d = 0; d < 64; d += 4) {
            float4 q4 = *(const float4*)(qrow + d);
            float4 p4 = *(const float4*)(pks + d);
            sum += q4.x * p4.x + q4.y * p4.y + q4.z * p4.z + q4.w * p4.w;
        }
        dinv_s[tid] = 1.0f / fmaxf(sum, 1e-6f);
    }
    __syncthreads();

    // ---- Phase B: out = S_masked . V + Q . Pkv (bf16x3)
    float o[8][4];
#pragma unroll
    for (int i = 0; i < 8; i++)
#pragma unroll
        for (int r = 0; r < 4; r++) o[i][r] = 0.f;

    // S.V : S accs become A-frags directly
#pragma unroll
    for (int np = 0; np < 4; np++) {
        uint32_t sh[4], sl[4];
#pragma unroll
        for (int half = 0; half < 2; half++) {
            int nt = 2 * np + half;
            uint32_t h0 = pack_bf16(s[nt][0], s[nt][1]);
            uint32_t h1 = pack_bf16(s[nt][2], s[nt][3]);
            sh[2 * half]     = h0;
            sh[2 * half + 1] = h1;
            float e0 = s[nt][0] - __uint_as_float(h0 << 16);
            float e1 = s[nt][1] - __uint_as_float(h0 & 0xffff0000u);
            float e2 = s[nt][2] - __uint_as_float(h1 << 16);
            float e3 = s[nt][3] - __uint_as_float(h1 & 0xffff0000u);
            sl[2 * half]     = pack_bf16(e0, e1);
            sl[2 * half + 1] = pack_bf16(e2, e3);
        }
#pragma unroll
        for (int nn = 0; nn < 4; nn++) {
            uint32_t vh[4], vl[4];
            uint32_t vo = SW128((uint32_t)((np * 16 + (tj_sel & 1) * 8 + tj_j) * 128 +
                                           (nn * 16 + (tj_sel >> 1) * 8) * 2));
            ldsm4t(vh, sb + AT_VHI + vo);
            ldsm4t(vl, sb + AT_VLO + vo);
            mma_bf16(o[2 * nn],     sh, vh);
            mma_bf16(o[2 * nn],     sh, vl);
            mma_bf16(o[2 * nn],     sl, vh);
            mma_bf16(o[2 * nn + 1], sh, vh + 2);
            mma_bf16(o[2 * nn + 1], sh, vl + 2);
            mma_bf16(o[2 * nn + 1], sl, vh + 2);
        }
    }

    // Q . Pkv
#pragma unroll
    for (int kt = 0; kt < 4; kt++) {
        uint32_t ah[4], al[4];
        uint32_t ao = SW128((uint32_t)((wm + la_r) * 128 + kt * 32 + la_h * 16));
        ldsm4(ah, sb + AT_QHI + ao);
        ldsm4(al, sb + AT_QLO + ao);
#pragma unroll
        for (int nn = 0; nn < 4; nn++) {
            uint32_t ph[4], pl[4];
            uint32_t po = SW128((uint32_t)((kt * 16 + (tj_sel & 1) * 8 + tj_j) * 128 +
                                           (nn * 16 + (tj_sel >> 1) * 8) * 2));
            ldsm4t(ph, sb + AT_PHI + po);
            ldsm4t(pl, sb + AT_PLO + po);
            mma_bf16(o[2 * nn],     ah, ph);
            mma_bf16(o[2 * nn],     ah, pl);
            mma_bf16(o[2 * nn],     al, ph);
            mma_bf16(o[2 * nn + 1], ah, ph + 2);
            mma_bf16(o[2 * nn + 1], ah, pl + 2);
            mma_bf16(o[2 * nn + 1], al, ph + 2);
        }
    }

    // ---- epilogue: scale by dinv, split hi/lo, store
    const float d0 = dinv_s[r0], d1 = dinv_s[r1];
    const int b = bh >> 4, h = bh & 15;
    const size_t ob0 = (size_t)(b * SEQ + t0 + r0) * DIM + h * 64;
    const size_t ob1 = (size_t)(b * SEQ + t0 + r1) * DIM + h * 64;
#pragma unroll
    for (int nt = 0; nt < 8; nt++) {
        int c0 = nt * 8 + (lane & 3) * 2;
        float x0 = o[nt][0] * d0, x1 = o[nt][1] * d0;
        float x2 = o[nt][2] * d1, x3 = o[nt][3] * d1;
        uint32_t h0 = pack_bf16(x0, x1);
        uint32_t h1 = pack_bf16(x2, x3);
        float e0 = x0 - __uint_as_float(h0 << 16);
        float e1 = x1 - __uint_as_float(h0 & 0xffff0000u);
        float e2 = x2 - __uint_as_float(h1 << 16);
        float e3 = x3 - __uint_as_float(h1 & 0xffff0000u);
        *(uint32_t*)(g_ahi + ob0 + c0) = h0;
        *(uint32_t*)(g_ahi + ob1 + c0) = h1;
        *(uint32_t*)(g_alo + ob0 + c0) = pack_bf16(e0, e1);
        *(uint32_t*)(g_alo + ob1 + c0) = pack_bf16(e2, e3);
    }
}

// ================= launch =================
extern "C" void kernel_launch(void* const* d_in, const int* in_sizes, int n_in,
                              void* d_out, int out_size)
{
    const float* x     = (const float*)d_in[0];
    const float* w_qkv = (const float*)d_in[1];
    const float* w_out = (const float*)d_in[2];
    float* out = (float*)d_out;

    __nv_bfloat16 *xhi, *xlo, *wqhi, *wqlo, *wohi, *wolo, *ahi, *alo;
    cudaGetSymbolAddress((void**)&xhi,  g_xhi);
    cudaGetSymbolAddress((void**)&xlo,  g_xlo);
    cudaGetSymbolAddress((void**)&wqhi, g_wqhi);
    cudaGetSymbolAddress((void**)&wqlo, g_wqlo);
    cudaGetSymbolAddress((void**)&wohi, g_wohi);
    cudaGetSymbolAddress((void**)&wolo, g_wolo);
    cudaGetSymbolAddress((void**)&ahi,  g_ahi);
    cudaGetSymbolAddress((void**)&alo,  g_alo);

    cudaFuncSetAttribute(gemm_tc<0>, cudaFuncAttributeMaxDynamicSharedMemorySize, GEMM_SMEM);
    cudaFuncSetAttribute(gemm_tc<1>, cudaFuncAttributeMaxDynamicSharedMemorySize, GEMM_SMEM);
    cudaFuncSetAttribute(attn_kernel, cudaFuncAttributeMaxDynamicSharedMemorySize, ATTN_SMEM);

    // 0) rope table + splits
    rope_init<<<(SEQ * 32) / 256, 256>>>();
    split_kernel<<<(MTOT * DIM) / (256 * 4), 256>>>(x, xhi, xlo);
    tsplit_kernel<<<dim3(3 * DIM / 32, DIM / 32), dim3(32, 8)>>>(w_qkv, wqhi, wqlo, DIM, 3 * DIM);
    tsplit_kernel<<<dim3(DIM / 32, DIM / 32), dim3(32, 8)>>>(w_out, wohi, wolo, DIM, DIM);

    // 1) QKV projection + fused RoPE/ELU featmap
    gemm_tc<1><<<dim3(3 * DIM / 128, MTOT / 128), 256, GEMM_SMEM>>>(xhi, xlo, wqhi, wqlo, nullptr, 3 * DIM);

    // 2) per-chunk K^T V and sum(k)
    chunksum_kernel<<<dim3(NCHUNK, BH), 256>>>();

    // 3) exclusive prefixes
    prefix_kernel<<<(BH * HD * HD) / 256, 256>>>();
    prefix_ks_kernel<<<(BH * HD) / 256, 256>>>();

    // 4) tensor-core chunk attention -> bf16 hi/lo activations
    attn_kernel<<<dim3(NCHUNK, BH), 128, ATTN_SMEM>>>();

    // 5) output projection
    gemm_tc<0><<<dim3(DIM / 128, MTOT / 128), 256, GEMM_SMEM>>>(ahi, alo, wohi, wolo, out, DIM);
}

// round 11
// speedup vs baseline: 1.3548x; 1.3548x over previous
#include <cuda_runtime.h>
#include <cuda_bf16.h>
#include <math.h>
#include <stdint.h>

#define BATCH 4
#define SEQ 4096
#define NH 16
#define HD 64
#define DIM 1024
#define BH (BATCH*NH)          // 64
#define CHUNK 64
#define NCHUNK (SEQ/CHUNK)     // 64
#define MTOT (BATCH*SEQ)       // 16384
#define FSCALE 0.35355339059327373f   // 64^-0.25

// ================= helpers =================
__device__ __forceinline__ uint32_t smem_u32(const void* p) {
    uint32_t a;
    asm("{ .reg .u64 t; cvta.to.shared.u64 t, %1; cvt.u32.u64 %0, t; }" : "=r"(a) : "l"(p));
    return a;
}
#define SW128(off) ((off) ^ (((off) >> 3) & 0x70))

__device__ __forceinline__ void cp16(uint32_t sa, const void* g) {
    asm volatile("cp.async.cg.shared.global [%0], [%1], 16;\n" :: "r"(sa), "l"(g) : "memory");
}
#define CP_COMMIT()  asm volatile("cp.async.commit_group;\n" ::: "memory")
#define CP_WAIT(n)   asm volatile("cp.async.wait_group %0;\n" :: "n"(n) : "memory")

__device__ __forceinline__ void ldsm4(uint32_t* r, uint32_t addr) {
    asm volatile("ldmatrix.sync.aligned.m8n8.x4.shared.b16 {%0,%1,%2,%3}, [%4];"
        : "=r"(r[0]), "=r"(r[1]), "=r"(r[2]), "=r"(r[3]) : "r"(addr));
}
__device__ __forceinline__ void mma_bf16(float* c, const uint32_t* a, const uint32_t* b) {
    asm volatile(
        "mma.sync.aligned.m16n8k16.row.col.f32.bf16.bf16.f32 "
        "{%0,%1,%2,%3}, {%4,%5,%6,%7}, {%8,%9}, {%0,%1,%2,%3};"
        : "+f"(c[0]), "+f"(c[1]), "+f"(c[2]), "+f"(c[3])
        : "r"(a[0]), "r"(a[1]), "r"(a[2]), "r"(a[3]), "r"(b[0]), "r"(b[1]));
}

// ================= scratch =================
__device__ float g_qf  [ (size_t)BH * SEQ * HD ];
__device__ float g_kf  [ (size_t)BH * SEQ * HD ];
__device__ float g_vf  [ (size_t)BH * SEQ * HD ];
__device__ float g_Skv [ (size_t)BH * NCHUNK * HD * HD ];
__device__ float g_Pkv [ (size_t)BH * NCHUNK * HD * HD ];
__device__ float g_Sks [ (size_t)BH * NCHUNK * HD ];
__device__ float g_Pks [ (size_t)BH * NCHUNK * HD ];
__device__ float g_cos [ (size_t)SEQ * 32 ];
__device__ float g_sin [ (size_t)SEQ * 32 ];
__device__ __nv_bfloat16 g_xhi [ (size_t)MTOT * DIM ];
__device__ __nv_bfloat16 g_xlo [ (size_t)MTOT * DIM ];
__device__ __nv_bfloat16 g_wqhi[ (size_t)3 * DIM * DIM ];
__device__ __nv_bfloat16 g_wqlo[ (size_t)3 * DIM * DIM ];
__device__ __nv_bfloat16 g_wohi[ (size_t)DIM * DIM ];
__device__ __nv_bfloat16 g_wolo[ (size_t)DIM * DIM ];
__device__ __nv_bfloat16 g_ahi [ (size_t)MTOT * DIM ];
__device__ __nv_bfloat16 g_alo [ (size_t)MTOT * DIM ];

// ================= rope table =================
__global__ __launch_bounds__(256) void rope_init()
{
    int idx = blockIdx.x * 256 + threadIdx.x;
    int j = idx & 31, t = idx >> 5;
    float inv = expf(-0.28782313662425572f * (float)j);
    float s, c;
    sincosf((float)t * inv, &s, &c);
    g_cos[idx] = c; g_sin[idx] = s;
}

// ================= split kernels =================
__global__ __launch_bounds__(256) void split_kernel(const float* __restrict__ in,
                                                    __nv_bfloat16* __restrict__ hi,
                                                    __nv_bfloat16* __restrict__ lo)
{
    size_t i = ((size_t)blockIdx.x * 256 + threadIdx.x) * 4;
    float4 v = *(const float4*)(in + i);
    float a[4] = {v.x, v.y, v.z, v.w};
    __nv_bfloat16 h[4], l[4];
#pragma unroll
    for (int j = 0; j < 4; j++) {
        h[j] = __float2bfloat16(a[j]);
        l[j] = __float2bfloat16(a[j] - __bfloat162float(h[j]));
    }
    *(uint2*)(hi + i) = *(uint2*)h;
    *(uint2*)(lo + i) = *(uint2*)l;
}

__global__ __launch_bounds__(256) void tsplit_kernel(const float* __restrict__ W,
                                                     __nv_bfloat16* __restrict__ hi,
                                                     __nv_bfloat16* __restrict__ lo,
                                                     int K, int N)
{
    __shared__ float t[32][33];
    int n0 = blockIdx.x * 32, k0 = blockIdx.y * 32;
    int tx = threadIdx.x, ty = threadIdx.y;
#pragma unroll
    for (int i = 0; i < 4; i++)
        t[ty + i * 8][tx] = W[(size_t)(k0 + ty + i * 8) * N + n0 + tx];
    __syncthreads();
#pragma unroll
    for (int i = 0; i < 4; i++) {
        float v = t[tx][ty + i * 8];
        __nv_bfloat16 h = __float2bfloat16(v);
        __nv_bfloat16 l = __float2bfloat16(v - __bfloat162float(h));
        size_t o = (size_t)(n0 + ty + i * 8) * K + k0 + tx;
        hi[o] = h; lo[o] = l;
    }
}

// ====== mma.sync bf16x3 GEMM: 4 warps, 64x64 warp tiles, KC=32, 3 stages ======
#define STAGE_BYTES 32768
#define NSTAGE 3
#define GEMM_SMEM (NSTAGE * STAGE_BYTES)
#define OFF_B 16384
#define KCH 32
#define NCH (1024 / KCH)

__device__ __forceinline__ void load_chunk(uint32_t stg,
    const __nv_bfloat16* __restrict__ Ahi, const __nv_bfloat16* __restrict__ Alo,
    const __nv_bfloat16* __restrict__ Bhi, const __nv_bfloat16* __restrict__ Blo,
    int m0, int n0, int k0, int tid)
{
#pragma unroll
    for (int i = 0; i < 16; i++) {
        int idx = tid + i * 128;              // 0..2047
        int tile = idx >> 10;
        int rem = idx & 1023;
        int row = rem >> 3, cv = rem & 7;
        uint32_t dst = stg + tile * OFF_B + SW128((uint32_t)(row * 128 + cv * 16));
        const __nv_bfloat16* base;
        int kk = k0 + (cv & 3) * 8;
        if (tile == 0) base = (cv < 4) ? Ahi : Alo;
        else           base = (cv < 4) ? Bhi : Blo;
        int grow = (tile == 0) ? (m0 + row) : (n0 + row);
        cp16(dst, base + (size_t)grow * 1024 + kk);
    }
}

template <int MODE>
__global__ __launch_bounds__(128, 2) void gemm_tc(
    const __nv_bfloat16* __restrict__ Ahi, const __nv_bfloat16* __restrict__ Alo,
    const __nv_bfloat16* __restrict__ Bhi, const __nv_bfloat16* __restrict__ Blo,
    float* __restrict__ C, int Ncols)
{
    extern __shared__ __align__(16) char smem[];
    const uint32_t sb = smem_u32(smem);
    const int tid = threadIdx.x;
    const int lane = tid & 31, wid = tid >> 5;
    const int wm = (wid & 1) * 64;      // warp m offset
    const int wn = (wid >> 1) * 64;     // warp n offset (64-wide)
    const int m0 = blockIdx.y * 128;
    const int n0 = blockIdx.x * 128;

    float acc[4][8][4];
#pragma unroll
    for (int i = 0; i < 4; i++)
#pragma unroll
        for (int j = 0; j < 8; j++)
#pragma unroll
            for (int r = 0; r < 4; r++) acc[i][j][r] = 0.f;

    const int la_r = lane & 15;
    const int la_h = lane >> 4;
    const int lb_row = ((lane >> 4) & 1) * 8 + (lane & 7);
    const int lb_k = (lane >> 3) & 1;

    load_chunk(sb,                   Ahi, Alo, Bhi, Blo, m0, n0, 0,        tid); CP_COMMIT();
    load_chunk(sb + STAGE_BYTES,     Ahi, Alo, Bhi, Blo, m0, n0, KCH,      tid); CP_COMMIT();
    load_chunk(sb + 2 * STAGE_BYTES, Ahi, Alo, Bhi, Blo, m0, n0, 2 * KCH,  tid); CP_COMMIT();

    int stage = 0;
    for (int c = 0; c < NCH; c++) {
        if (c <= NCH - 3)      { CP_WAIT(2); }
        else if (c == NCH - 2) { CP_WAIT(1); }
        else                   { CP_WAIT(0); }
        __syncthreads();

        const uint32_t stg = sb + stage * STAGE_BYTES;
#pragma unroll
        for (int ks = 0; ks < 2; ks++) {
            const int kb = ks * 32 + la_h * 16;
            uint32_t ahi[4][4], alo[4][4];
#pragma unroll
            for (int mt = 0; mt < 4; mt++) {
                uint32_t ro = (uint32_t)((wm + mt * 16 + la_r) * 128);
                ldsm4(ahi[mt], stg + SW128(ro + kb));
                ldsm4(alo[mt], stg + SW128(ro + kb + 64));
            }
            const int kbb = ks * 32 + lb_k * 16;
#pragma unroll
            for (int ntp = 0; ntp < 4; ntp++) {
                uint32_t bh[4], bl[4];
                uint32_t ro = (uint32_t)((wn + ntp * 16 + lb_row) * 128);
                ldsm4(bh, stg + OFF_B + SW128(ro + kbb));
                ldsm4(bl, stg + OFF_B + SW128(ro + kbb + 64));
#pragma unroll
                for (int mt = 0; mt < 4; mt++) {
                    mma_bf16(acc[mt][2 * ntp],     ahi[mt], bh);
                    mma_bf16(acc[mt][2 * ntp],     ahi[mt], bl);
                    mma_bf16(acc[mt][2 * ntp],     alo[mt], bh);
                    mma_bf16(acc[mt][2 * ntp + 1], ahi[mt], bh + 2);
                    mma_bf16(acc[mt][2 * ntp + 1], ahi[mt], bl + 2);
                    mma_bf16(acc[mt][2 * ntp + 1], alo[mt], bh + 2);
                }
            }
        }
        __syncthreads();
        if (c + 3 < NCH) {
            load_chunk(sb + stage * STAGE_BYTES, Ahi, Alo, Bhi, Blo, m0, n0, (c + 3) * KCH, tid);
            CP_COMMIT();
        }
        stage = (stage + 1 == NSTAGE) ? 0 : stage + 1;
    }

    const int rquad = lane >> 2, cpair = (lane & 3) * 2;

    if (MODE == 0) {
#pragma unroll
        for (int mt = 0; mt < 4; mt++) {
#pragma unroll
            for (int nt = 0; nt < 8; nt++) {
                int row = m0 + wm + mt * 16 + rquad;
                int col = n0 + wn + nt * 8 + cpair;
                float2* p0 = (float2*)(C + (size_t)row * Ncols + col);
                float2* p1 = (float2*)(C + (size_t)(row + 8) * Ncols + col);
                *p0 = make_float2(acc[mt][nt][0], acc[mt][nt][1]);
                *p1 = make_float2(acc[mt][nt][2], acc[mt][nt][3]);
            }
        }
    } else {
        float* ct = (float*)smem;   // [128][128]
#pragma unroll
        for (int mt = 0; mt < 4; mt++) {
#pragma unroll
            for (int nt = 0; nt < 8; nt++) {
                int row = wm + mt * 16 + rquad;
                int col = wn + nt * 8 + cpair;
                *(float2*)&ct[row * 128 + col]       = make_float2(acc[mt][nt][0], acc[mt][nt][1]);
                *(float2*)&ct[(row + 8) * 128 + col] = make_float2(acc[mt][nt][2], acc[mt][nt][3]);
            }
        }
        __syncthreads();

        const int region = n0 >> 10;
        const int h0 = (n0 & 1023) >> 6;

        if (region < 2) {
            float* dst = (region == 0) ? g_qf : g_kf;
#pragma unroll 4
            for (int i = 0; i < 64; i++) {
                int p = i * 128 + tid;        // 8192 rope pairs
                int row = p >> 6;
                int w = p & 63;
                int hh = w >> 5;
                int j = w & 31;
                float x1 = ct[row * 128 + hh * 64 + j];
                float x2 = ct[row * 128 + hh * 64 + j + 32];
                int gm = m0 + row;
                int t = gm & 4095, b = gm >> 12;
                float cc = g_cos[t * 32 + j];
                float s  = g_sin[t * 32 + j];
                float a1 = (x1 * cc - x2 * s) * FSCALE;
                float a2 = (x1 * s + x2 * cc) * FSCALE;
                a1 = (a1 > 0.f) ? a1 + 1.f : __expf(a1);
                a2 = (a2 > 0.f) ? a2 + 1.f : __expf(a2);
                size_t o = ((size_t)(b * NH + h0 + hh) * SEQ + t) * 64 + j;
                dst[o] = a1; dst[o + 32] = a2;
            }
        } else {
#pragma unroll 4
            for (int i = 0; i < 128; i++) {
                int p = i * 128 + tid;        // 16384 elems
                int row = p >> 7, col = p & 127;
                int gm = m0 + row;
                int t = gm & 4095, b = gm >> 12;
                size_t o = ((size_t)(b * NH + h0 + (col >> 6)) * SEQ + t) * 64 + (col & 63);
                g_vf[o] = ct[row * 128 + col];
            }
        }
    }
}

// ================= per-chunk local sums =================
__global__ __launch_bounds__(256) void chunksum_kernel()
{
    const int c = blockIdx.x, bh = blockIdx.y;
    const int tid = threadIdx.x;
    __shared__ __align__(16) float ks[CHUNK][HD];
    __shared__ __align__(16) float vs[CHUNK][HD];

    const float* Kg = g_kf + ((size_t)bh * SEQ + c * CHUNK) * HD;
    const float* Vg = g_vf + ((size_t)bh * SEQ + c * CHUNK) * HD;

    const int row = tid >> 2, f0 = tid & 3;
#pragma unroll
    for (int i = 0; i < 4; i++) {
        int f = (f0 + i * 4) * 4;
        *(float4*)&ks[row][f] = *(const float4*)(Kg + row * 64 + f);
        *(float4*)&vs[row][f] = *(const float4*)(Vg + row * 64 + f);
    }
    __syncthreads();

    const int m = tid & 63;
    const int dbase = (tid >> 6) * 16;
    float acc[16];
#pragma unroll
    for (int i = 0; i < 16; i++) acc[i] = 0.f;

    for (int t = 0; t < CHUNK; t++) {
        float v = vs[t][m];
#pragma unroll
        for (int w = 0; w < 4; w++) {
            float4 kk = *(float4*)&ks[t][dbase + w * 4];
            acc[w * 4 + 0] += kk.x * v;
            acc[w * 4 + 1] += kk.y * v;
            acc[w * 4 + 2] += kk.z * v;
            acc[w * 4 + 3] += kk.w * v;
        }
    }

    float* S = g_Skv + ((size_t)bh * NCHUNK + c) * (HD * HD);
#pragma unroll
    for (int d = 0; d < 16; d++)
        S[(dbase + d) * 64 + m] = acc[d];

    if (tid < 64) {
        float s = 0.f;
        for (int t = 0; t < CHUNK; t++) s += ks[t][tid];
        g_Sks[((size_t)bh * NCHUNK + c) * HD + tid] = s;
    }
}

// ================= exclusive prefixes =================
__global__ __launch_bounds__(256) void prefix_kernel()
{
    int e = blockIdx.x * 256 + threadIdx.x;
    int bh = e >> 12, el = e & 4095;
    float run = 0.f;
    for (int c = 0; c < NCHUNK; c++) {
        size_t i = ((size_t)bh * NCHUNK + c) * (HD * HD) + el;
        g_Pkv[i] = run;
        run += g_Skv[i];
    }
}
__global__ __launch_bounds__(256) void prefix_ks_kernel()
{
    int e = blockIdx.x * 256 + threadIdx.x;
    int bh = e >> 6, d = e & 63;
    float run = 0.f;
    for (int c = 0; c < NCHUNK; c++) {
        size_t i = ((size_t)bh * NCHUNK + c) * HD + d;
        g_Pks[i] = run;
        run += g_Sks[i];
    }
}

// ================= chunk attention (R9 SIMT version) =================
__global__ __launch_bounds__(256) void attn_kernel()
{
    const int c = blockIdx.x, bh = blockIdx.y;
    const int tid = threadIdx.x;
    extern __shared__ float sm[];
    float* Qt   = sm;
    float* Kt   = Qt + 64 * 68;
    float* At   = Kt + 64 * 68;
    float* Vs   = At + 64 * 68;
    float* Ps   = Vs + 64 * 64;
    float* pks  = Ps + 64 * 64;
    float* dinv = pks + 64;

    const int t0 = c * CHUNK;
    const float* Qg   = g_qf + ((size_t)bh * SEQ + t0) * HD;
    const float* Kg   = g_kf + ((size_t)bh * SEQ + t0) * HD;
    const float* Vg   = g_vf + ((size_t)bh * SEQ + t0) * HD;
    const float* Pg   = g_Pkv + ((size_t)bh * NCHUNK + c) * (HD * HD);
    const float* pksg = g_Pks + ((size_t)bh * NCHUNK + c) * HD;

    const int row = tid >> 2, f0 = tid & 3;
#pragma unroll
    for (int i = 0; i < 4; i++) {
        int d = (f0 + i * 4) * 4;
        float4 q4 = *(const float4*)(Qg + row * 64 + d);
        Qt[(d + 0) * 68 + row] = q4.x;
        Qt[(d + 1) * 68 + row] = q4.y;
        Qt[(d + 2) * 68 + row] = q4.z;
        Qt[(d + 3) * 68 + row] = q4.w;
        float4 k4 = *(const float4*)(Kg + row * 64 + d);
        Kt[(d + 0) * 68 + row] = k4.x;
        Kt[(d + 1) * 68 + row] = k4.y;
        Kt[(d + 2) * 68 + row] = k4.z;
        Kt[(d + 3) * 68 + row] = k4.w;
        *(float4*)&Vs[row * 64 + d] = *(const float4*)(Vg + row * 64 + d);
        *(float4*)&Ps[row * 64 + d] = *(const float4*)(Pg + row * 64 + d);
    }
    if (tid < 64) pks[tid] = pksg[tid];
    __syncthreads();

    const int ty = tid >> 4, tx = tid & 15;
    const int rb = ty * 4, cb = tx * 4;

    float a[4][4];
#pragma unroll
    for (int i = 0; i < 4; i++)
#pragma unroll
        for (int j = 0; j < 4; j++) a[i][j] = 0.f;

    for (int d = 0; d < 64; d++) {
        float4 q4 = *(float4*)&Qt[d * 68 + rb];
        float4 k4 = *(float4*)&Kt[d * 68 + cb];
        float qv[4] = {q4.x, q4.y, q4.z, q4.w};
        float kv[4] = {k4.x, k4.y, k4.z, k4.w};
#pragma unroll
        for (int i = 0; i < 4; i++)
#pragma unroll
            for (int j = 0; j < 4; j++)
                a[i][j] += qv[i] * kv[j];
    }
#pragma unroll
    for (int i = 0; i < 4; i++)
#pragma unroll
        for (int j = 0; j < 4; j++) {
            int ti = rb + i, tj = cb + j;
            At[tj * 68 + ti] = (tj <= ti) ? a[i][j] : 0.f;
        }
    __syncthreads();

    if (tid < 64) {
        float s = 0.f;
        for (int tj = 0; tj < 64; tj++) s += At[tj * 68 + tid];
        for (int d = 0; d < 64; d++) s += Qt[d * 68 + tid] * pks[d];
        dinv[tid] = 1.0f / fmaxf(s, 1e-6f);
    }
    __syncthreads();

    float o[4][4];
#pragma unroll
    for (int i = 0; i < 4; i++)
#pragma unroll
        for (int j = 0; j < 4; j++) o[i][j] = 0.f;

    for (int tj = 0; tj < 64; tj++) {
        float4 a4 = *(float4*)&At[tj * 68 + rb];
        float4 v4 = *(float4*)&Vs[tj * 64 + cb];
        float av[4] = {a4.x, a4.y, a4.z, a4.w};
        float vv[4] = {v4.x, v4.y, v4.z, v4.w};
#pragma unroll
        for (int i = 0; i < 4; i++)
#pragma unroll
            for (int j = 0; j < 4; j++)
                o[i][j] += av[i] * vv[j];
    }
    for (int d = 0; d < 64; d++) {
        float4 q4 = *(float4*)&Qt[d * 68 + rb];
        float4 p4 = *(float4*)&Ps[d * 64 + cb];
        float qv[4] = {q4.x, q4.y, q4.z, q4.w};
        float pv[4] = {p4.x, p4.y, p4.z, p4.w};
#pragma unroll
        for (int i = 0; i < 4; i++)
#pragma unroll
            for (int j = 0; j < 4; j++)
                o[i][j] += qv[i] * pv[j];
    }

    const int b = bh >> 4, h = bh & 15;
#pragma unroll
    for (int i = 0; i < 4; i++) {
        int ti = rb + i;
        float di = dinv[ti];
        __nv_bfloat16 hv[4], lv[4];
#pragma unroll
        for (int j = 0; j < 4; j++) {
            float v = o[i][j] * di;
            hv[j] = __float2bfloat16(v);
            lv[j] = __float2bfloat16(v - __bfloat162float(hv[j]));
        }
        size_t oidx = (size_t)(b * SEQ + t0 + ti) * DIM + h * 64 + cb;
        *(uint2*)(g_ahi + oidx) = *(uint2*)hv;
        *(uint2*)(g_alo + oidx) = *(uint2*)lv;
    }
}

// ================= launch =================
extern "C" void kernel_launch(void* const* d_in, const int* in_sizes, int n_in,
                              void* d_out, int out_size)
{
    const float* x     = (const float*)d_in[0];
    const float* w_qkv = (const float*)d_in[1];
    const float* w_out = (const float*)d_in[2];
    float* out = (float*)d_out;

    __nv_bfloat16 *xhi, *xlo, *wqhi, *wqlo, *wohi, *wolo, *ahi, *alo;
    cudaGetSymbolAddress((void**)&xhi,  g_xhi);
    cudaGetSymbolAddress((void**)&xlo,  g_xlo);
    cudaGetSymbolAddress((void**)&wqhi, g_wqhi);
    cudaGetSymbolAddress((void**)&wqlo, g_wqlo);
    cudaGetSymbolAddress((void**)&wohi, g_wohi);
    cudaGetSymbolAddress((void**)&wolo, g_wolo);
    cudaGetSymbolAddress((void**)&ahi,  g_ahi);
    cudaGetSymbolAddress((void**)&alo,  g_alo);

    cudaFuncSetAttribute(gemm_tc<0>, cudaFuncAttributeMaxDynamicSharedMemorySize, GEMM_SMEM);
    cudaFuncSetAttribute(gemm_tc<1>, cudaFuncAttributeMaxDynamicSharedMemorySize, GEMM_SMEM);
    const int attn_smem = (64 * 68 * 3 + 64 * 64 * 2 + 128) * 4;
    cudaFuncSetAttribute(attn_kernel, cudaFuncAttributeMaxDynamicSharedMemorySize, attn_smem);

    // 0) rope table + splits
    rope_init<<<(SEQ * 32) / 256, 256>>>();
    split_kernel<<<(MTOT * DIM) / (256 * 4), 256>>>(x, xhi, xlo);
    tsplit_kernel<<<dim3(3 * DIM / 32, DIM / 32), dim3(32, 8)>>>(w_qkv, wqhi, wqlo, DIM, 3 * DIM);
    tsplit_kernel<<<dim3(DIM / 32, DIM / 32), dim3(32, 8)>>>(w_out, wohi, wolo, DIM, DIM);

    // 1) QKV projection + fused RoPE/ELU featmap
    gemm_tc<1><<<dim3(3 * DIM / 128, MTOT / 128), 128, GEMM_SMEM>>>(xhi, xlo, wqhi, wqlo, nullptr, 3 * DIM);

    // 2) per-chunk K^T V and sum(k)
    chunksum_kernel<<<dim3(NCHUNK, BH), 256>>>();

    // 3) exclusive prefixes
    prefix_kernel<<<(BH * HD * HD) / 256, 256>>>();
    prefix_ks_kernel<<<(BH * HD) / 256, 256>>>();

    // 4) chunk attention -> bf16 hi/lo activations
    attn_kernel<<<dim3(NCHUNK, BH), 256, attn_smem>>>();

    // 5) output projection
    gemm_tc<0><<<dim3(DIM / 128, MTOT / 128), 128, GEMM_SMEM>>>(ahi, alo, wohi, wolo, out, DIM);
}

// round 15
// speedup vs baseline: 1.4113x; 1.0417x over previous
#include <cuda_runtime.h>
#include <cuda_bf16.h>
#include <math.h>
#include <stdint.h>

#define BATCH 4
#define SEQ 4096
#define NH 16
#define HD 64
#define DIM 1024
#define BH (BATCH*NH)          // 64
#define CHUNK 64
#define NCHUNK (SEQ/CHUNK)     // 64
#define MTOT (BATCH*SEQ)       // 16384
#define FSCALE 0.35355339059327373f   // 64^-0.25

// ================= helpers =================
__device__ __forceinline__ uint32_t smem_u32(const void* p) {
    uint32_t a;
    asm("{ .reg .u64 t; cvta.to.shared.u64 t, %1; cvt.u32.u64 %0, t; }" : "=r"(a) : "l"(p));
    return a;
}
#define SW128(off) ((off) ^ (((off) >> 3) & 0x70))

__device__ __forceinline__ void cp16(uint32_t sa, const void* g) {
    asm volatile("cp.async.cg.shared.global [%0], [%1], 16;\n" :: "r"(sa), "l"(g) : "memory");
}
#define CP_COMMIT()  asm volatile("cp.async.commit_group;\n" ::: "memory")
#define CP_WAIT(n)   asm volatile("cp.async.wait_group %0;\n" :: "n"(n) : "memory")

__device__ __forceinline__ void ldsm4(uint32_t* r, uint32_t addr) {
    asm volatile("ldmatrix.sync.aligned.m8n8.x4.shared.b16 {%0,%1,%2,%3}, [%4];"
        : "=r"(r[0]), "=r"(r[1]), "=r"(r[2]), "=r"(r[3]) : "r"(addr));
}
__device__ __forceinline__ void mma_bf16(float* c, const uint32_t* a, const uint32_t* b) {
    asm volatile(
        "mma.sync.aligned.m16n8k16.row.col.f32.bf16.bf16.f32 "
        "{%0,%1,%2,%3}, {%4,%5,%6,%7}, {%8,%9}, {%0,%1,%2,%3};"
        : "+f"(c[0]), "+f"(c[1]), "+f"(c[2]), "+f"(c[3])
        : "r"(a[0]), "r"(a[1]), "r"(a[2]), "r"(a[3]), "r"(b[0]), "r"(b[1]));
}

// ================= scratch =================
__device__ float g_qf  [ (size_t)BH * SEQ * HD ];
__device__ float g_kf  [ (size_t)BH * SEQ * HD ];
__device__ float g_vf  [ (size_t)BH * SEQ * HD ];
__device__ float g_Skv [ (size_t)BH * NCHUNK * HD * HD ];
__device__ float g_Pkv [ (size_t)BH * NCHUNK * HD * HD ];
__device__ float g_Sks [ (size_t)BH * NCHUNK * HD ];
__device__ float g_Pks [ (size_t)BH * NCHUNK * HD ];
__device__ float g_cos [ (size_t)SEQ * 32 ];
__device__ float g_sin [ (size_t)SEQ * 32 ];
__device__ __nv_bfloat16 g_xhi [ (size_t)MTOT * DIM ];
__device__ __nv_bfloat16 g_xlo [ (size_t)MTOT * DIM ];
__device__ __nv_bfloat16 g_wqhi[ (size_t)3 * DIM * DIM ];
__device__ __nv_bfloat16 g_wqlo[ (size_t)3 * DIM * DIM ];
__device__ __nv_bfloat16 g_wohi[ (size_t)DIM * DIM ];
__device__ __nv_bfloat16 g_wolo[ (size_t)DIM * DIM ];
__device__ __nv_bfloat16 g_ahi [ (size_t)MTOT * DIM ];
__device__ __nv_bfloat16 g_alo [ (size_t)MTOT * DIM ];

// ================= rope table =================
__global__ __launch_bounds__(256) void rope_init()
{
    int idx = blockIdx.x * 256 + threadIdx.x;
    int j = idx & 31, t = idx >> 5;
    float inv = expf(-0.28782313662425572f * (float)j);
    float s, c;
    sincosf((float)t * inv, &s, &c);
    g_cos[idx] = c; g_sin[idx] = s;
}

// ================= split kernels =================
__global__ __launch_bounds__(256) void split_kernel(const float* __restrict__ in,
                                                    __nv_bfloat16* __restrict__ hi,
                                                    __nv_bfloat16* __restrict__ lo)
{
    size_t i = ((size_t)blockIdx.x * 256 + threadIdx.x) * 4;
    float4 v = *(const float4*)(in + i);
    float a[4] = {v.x, v.y, v.z, v.w};
    __nv_bfloat16 h[4], l[4];
#pragma unroll
    for (int j = 0; j < 4; j++) {
        h[j] = __float2bfloat16(a[j]);
        l[j] = __float2bfloat16(a[j] - __bfloat162float(h[j]));
    }
    *(uint2*)(hi + i) = *(uint2*)h;
    *(uint2*)(lo + i) = *(uint2*)l;
}

__global__ __launch_bounds__(256) void tsplit_kernel(const float* __restrict__ W,
                                                     __nv_bfloat16* __restrict__ hi,
                                                     __nv_bfloat16* __restrict__ lo,
                                                     int K, int N)
{
    __shared__ float t[32][33];
    int n0 = blockIdx.x * 32, k0 = blockIdx.y * 32;
    int tx = threadIdx.x, ty = threadIdx.y;
#pragma unroll
    for (int i = 0; i < 4; i++)
        t[ty + i * 8][tx] = W[(size_t)(k0 + ty + i * 8) * N + n0 + tx];
    __syncthreads();
#pragma unroll
    for (int i = 0; i < 4; i++) {
        float v = t[tx][ty + i * 8];
        __nv_bfloat16 h = __float2bfloat16(v);
        __nv_bfloat16 l = __float2bfloat16(v - __bfloat162float(h));
        size_t o = (size_t)(n0 + ty + i * 8) * K + k0 + tx;
        hi[o] = h; lo[o] = l;
    }
}

// ====== mma.sync bf16x3 GEMM: 8 warps 64x32, KC=32, 3 buffers, 1 sync/iter ======
#define STAGE_BYTES 32768
#define NSTAGE 3
#define GEMM_SMEM (NSTAGE * STAGE_BYTES)
#define OFF_B 16384
#define KCH 32
#define NCH (1024 / KCH)

__device__ __forceinline__ void load_chunk(uint32_t stg,
    const __nv_bfloat16* __restrict__ Ahi, const __nv_bfloat16* __restrict__ Alo,
    const __nv_bfloat16* __restrict__ Bhi, const __nv_bfloat16* __restrict__ Blo,
    int m0, int n0, int k0, int tid)
{
#pragma unroll
    for (int i = 0; i < 8; i++) {
        int idx = tid + i * 256;              // 0..2047
        int tile = idx >> 10;
        int rem = idx & 1023;
        int row = rem >> 3, cv = rem & 7;
        uint32_t dst = stg + tile * OFF_B + SW128((uint32_t)(row * 128 + cv * 16));
        const __nv_bfloat16* base;
        int kk = k0 + (cv & 3) * 8;
        if (tile == 0) base = (cv < 4) ? Ahi : Alo;
        else           base = (cv < 4) ? Bhi : Blo;
        int grow = (tile == 0) ? (m0 + row) : (n0 + row);
        cp16(dst, base + (size_t)grow * 1024 + kk);
    }
}

template <int MODE>
__global__ __launch_bounds__(256, 2) void gemm_tc(
    const __nv_bfloat16* __restrict__ Ahi, const __nv_bfloat16* __restrict__ Alo,
    const __nv_bfloat16* __restrict__ Bhi, const __nv_bfloat16* __restrict__ Blo,
    float* __restrict__ C, int Ncols)
{
    extern __shared__ __align__(16) char smem[];
    const uint32_t sb = smem_u32(smem);
    const int tid = threadIdx.x;
    const int lane = tid & 31, wid = tid >> 5;
    const int wm = (wid & 1) * 64;
    const int wn = (wid >> 1) * 32;
    const int m0 = blockIdx.y * 128;
    const int n0 = blockIdx.x * 128;

    float acc[4][4][4];
#pragma unroll
    for (int i = 0; i < 4; i++)
#pragma unroll
        for (int j = 0; j < 4; j++)
#pragma unroll
            for (int r = 0; r < 4; r++) acc[i][j][r] = 0.f;

    const int la_r = lane & 15;
    const int la_h = lane >> 4;
    const int lb_row = ((lane >> 4) & 1) * 8 + (lane & 7);
    const int lb_k = (lane >> 3) & 1;

    // prologue: prefetch chunks 0,1 (distance 2, 3 buffers)
    load_chunk(sb,               Ahi, Alo, Bhi, Blo, m0, n0, 0,   tid); CP_COMMIT();
    load_chunk(sb + STAGE_BYTES, Ahi, Alo, Bhi, Blo, m0, n0, KCH, tid); CP_COMMIT();

    int stage = 0;
    for (int c = 0; c < NCH; c++) {
        if (c == NCH - 1) { CP_WAIT(0); } else { CP_WAIT(1); }
        __syncthreads();   // single barrier: chunk c visible + stage (c+2)%3 readers done
        if (c + 2 < NCH) {
            int ws = c + 2 - ((c + 2) / NSTAGE) * NSTAGE;   // (c+2)%3
            load_chunk(sb + ws * STAGE_BYTES, Ahi, Alo, Bhi, Blo, m0, n0, (c + 2) * KCH, tid);
            CP_COMMIT();
        }

        const uint32_t stg = sb + stage * STAGE_BYTES;
#pragma unroll
        for (int ks = 0; ks < 2; ks++) {
            const int kb = ks * 32 + la_h * 16;
            uint32_t ahi[4][4], alo[4][4];
#pragma unroll
            for (int mt = 0; mt < 4; mt++) {
                uint32_t ro = (uint32_t)((wm + mt * 16 + la_r) * 128);
                ldsm4(ahi[mt], stg + SW128(ro + kb));
                ldsm4(alo[mt], stg + SW128(ro + kb + 64));
            }
            const int kbb = ks * 32 + lb_k * 16;
#pragma unroll
            for (int ntp = 0; ntp < 2; ntp++) {
                uint32_t bh[4], bl[4];
                uint32_t ro = (uint32_t)((wn + ntp * 16 + lb_row) * 128);
                ldsm4(bh, stg + OFF_B + SW128(ro + kbb));
                ldsm4(bl, stg + OFF_B + SW128(ro + kbb + 64));
#pragma unroll
                for (int mt = 0; mt < 4; mt++) {
                    mma_bf16(acc[mt][2 * ntp],     ahi[mt], bh);
                    mma_bf16(acc[mt][2 * ntp],     ahi[mt], bl);
                    mma_bf16(acc[mt][2 * ntp],     alo[mt], bh);
                    mma_bf16(acc[mt][2 * ntp + 1], ahi[mt], bh + 2);
                    mma_bf16(acc[mt][2 * ntp + 1], ahi[mt], bl + 2);
                    mma_bf16(acc[mt][2 * ntp + 1], alo[mt], bh + 2);
                }
            }
        }
        stage = (stage + 1 == NSTAGE) ? 0 : stage + 1;
    }

    const int rquad = lane >> 2, cpair = (lane & 3) * 2;

    if (MODE == 0) {
#pragma unroll
        for (int mt = 0; mt < 4; mt++) {
#pragma unroll
            for (int nt = 0; nt < 4; nt++) {
                int row = m0 + wm + mt * 16 + rquad;
                int col = n0 + wn + nt * 8 + cpair;
                float2* p0 = (float2*)(C + (size_t)row * Ncols + col);
                float2* p1 = (float2*)(C + (size_t)(row + 8) * Ncols + col);
                *p0 = make_float2(acc[mt][nt][0], acc[mt][nt][1]);
                *p1 = make_float2(acc[mt][nt][2], acc[mt][nt][3]);
            }
        }
    } else {
        // fused featmap epilogue: stage smem reused for fp32 tile
        float* ct = (float*)smem;   // [128][128]
        __syncthreads();            // last chunk's ldmatrix reads done before overwrite
#pragma unroll
        for (int mt = 0; mt < 4; mt++) {
#pragma unroll
            for (int nt = 0; nt < 4; nt++) {
                int row = wm + mt * 16 + rquad;
                int col = wn + nt * 8 + cpair;
                *(float2*)&ct[row * 128 + col]       = make_float2(acc[mt][nt][0], acc[mt][nt][1]);
                *(float2*)&ct[(row + 8) * 128 + col] = make_float2(acc[mt][nt][2], acc[mt][nt][3]);
            }
        }
        __syncthreads();

        const int region = n0 >> 10;
        const int h0 = (n0 & 1023) >> 6;

        if (region < 2) {
            float* dst = (region == 0) ? g_qf : g_kf;
#pragma unroll 4
            for (int i = 0; i < 32; i++) {
                int p = i * 256 + tid;        // 8192 rope pairs
                int row = p >> 6;
                int w = p & 63;
                int hh = w >> 5;
                int j = w & 31;
                float x1 = ct[row * 128 + hh * 64 + j];
                float x2 = ct[row * 128 + hh * 64 + j + 32];
                int gm = m0 + row;
                int t = gm & 4095, b = gm >> 12;
                float cc = g_cos[t * 32 + j];
                float s  = g_sin[t * 32 + j];
                float a1 = (x1 * cc - x2 * s) * FSCALE;
                float a2 = (x1 * s + x2 * cc) * FSCALE;
                a1 = (a1 > 0.f) ? a1 + 1.f : __expf(a1);
                a2 = (a2 > 0.f) ? a2 + 1.f : __expf(a2);
                size_t o = ((size_t)(b * NH + h0 + hh) * SEQ + t) * 64 + j;
                dst[o] = a1; dst[o + 32] = a2;
            }
        } else {
#pragma unroll 4
            for (int i = 0; i < 64; i++) {
                int p = i * 256 + tid;
                int row = p >> 7, col = p & 127;
                int gm = m0 + row;
                int t = gm & 4095, b = gm >> 12;
                size_t o = ((size_t)(b * NH + h0 + (col >> 6)) * SEQ + t) * 64 + (col & 63);
                g_vf[o] = ct[row * 128 + col];
            }
        }
    }
}

// ================= per-chunk local sums =================
__global__ __launch_bounds__(256) void chunksum_kernel()
{
    const int c = blockIdx.x, bh = blockIdx.y;
    const int tid = threadIdx.x;
    __shared__ __align__(16) float ks[CHUNK][HD];
    __shared__ __align__(16) float vs[CHUNK][HD];

    const float* Kg = g_kf + ((size_t)bh * SEQ + c * CHUNK) * HD;
    const float* Vg = g_vf + ((size_t)bh * SEQ + c * CHUNK) * HD;

    const int row = tid >> 2, f0 = tid & 3;
#pragma unroll
    for (int i = 0; i < 4; i++) {
        int f = (f0 + i * 4) * 4;
        *(float4*)&ks[row][f] = *(const float4*)(Kg + row * 64 + f);
        *(float4*)&vs[row][f] = *(const float4*)(Vg + row * 64 + f);
    }
    __syncthreads();

    const int m = tid & 63;
    const int dbase = (tid >> 6) * 16;
    float acc[16];
#pragma unroll
    for (int i = 0; i < 16; i++) acc[i] = 0.f;

    for (int t = 0; t < CHUNK; t++) {
        float v = vs[t][m];
#pragma unroll
        for (int w = 0; w < 4; w++) {
            float4 kk = *(float4*)&ks[t][dbase + w * 4];
            acc[w * 4 + 0] += kk.x * v;
            acc[w * 4 + 1] += kk.y * v;
            acc[w * 4 + 2] += kk.z * v;
            acc[w * 4 + 3] += kk.w * v;
        }
    }

    float* S = g_Skv + ((size_t)bh * NCHUNK + c) * (HD * HD);
#pragma unroll
    for (int d = 0; d < 16; d++)
        S[(dbase + d) * 64 + m] = acc[d];

    if (tid < 64) {
        float s = 0.f;
        for (int t = 0; t < CHUNK; t++) s += ks[t][tid];
        g_Sks[((size_t)bh * NCHUNK + c) * HD + tid] = s;
    }
}

// ================= merged exclusive prefixes =================
// blocks [0,1024): Pkv chains; blocks [1024,1040): Pks chains
__global__ __launch_bounds__(256) void prefix_kernel()
{
    if (blockIdx.x < 1024) {
        int e = blockIdx.x * 256 + threadIdx.x;
        int bh = e >> 12, el = e & 4095;
        float run = 0.f;
        for (int c = 0; c < NCHUNK; c++) {
            size_t i = ((size_t)bh * NCHUNK + c) * (HD * HD) + el;
            g_Pkv[i] = run;
            run += g_Skv[i];
        }
    } else {
        int e = (blockIdx.x - 1024) * 256 + threadIdx.x;
        int bh = e >> 6, d = e & 63;
        float run = 0.f;
        for (int c = 0; c < NCHUNK; c++) {
            size_t i = ((size_t)bh * NCHUNK + c) * HD + d;
            g_Pks[i] = run;
            run += g_Sks[i];
        }
    }
}

// ================= chunk attention (SIMT, R9) =================
__global__ __launch_bounds__(256) void attn_kernel()
{
    const int c = blockIdx.x, bh = blockIdx.y;
    const int tid = threadIdx.x;
    extern __shared__ float sm[];
    float* Qt   = sm;
    float* Kt   = Qt + 64 * 68;
    float* At   = Kt + 64 * 68;
    float* Vs   = At + 64 * 68;
    float* Ps   = Vs + 64 * 64;
    float* pks  = Ps + 64 * 64;
    float* dinv = pks + 64;

    const int t0 = c * CHUNK;
    const float* Qg   = g_qf + ((size_t)bh * SEQ + t0) * HD;
    const float* Kg   = g_kf + ((size_t)bh * SEQ + t0) * HD;
    const float* Vg   = g_vf + ((size_t)bh * SEQ + t0) * HD;
    const float* Pg   = g_Pkv + ((size_t)bh * NCHUNK + c) * (HD * HD);
    const float* pksg = g_Pks + ((size_t)bh * NCHUNK + c) * HD;

    const int row = tid >> 2, f0 = tid & 3;
#pragma unroll
    for (int i = 0; i < 4; i++) {
        int d = (f0 + i * 4) * 4;
        float4 q4 = *(const float4*)(Qg + row * 64 + d);
        Qt[(d + 0) * 68 + row] = q4.x;
        Qt[(d + 1) * 68 + row] = q4.y;
        Qt[(d + 2) * 68 + row] = q4.z;
        Qt[(d + 3) * 68 + row] = q4.w;
        float4 k4 = *(const float4*)(Kg + row * 64 + d);
        Kt[(d + 0) * 68 + row] = k4.x;
        Kt[(d + 1) * 68 + row] = k4.y;
        Kt[(d + 2) * 68 + row] = k4.z;
        Kt[(d + 3) * 68 + row] = k4.w;
        *(float4*)&Vs[row * 64 + d] = *(const float4*)(Vg + row * 64 + d);
        *(float4*)&Ps[row * 64 + d] = *(const float4*)(Pg + row * 64 + d);
    }
    if (tid < 64) pks[tid] = pksg[tid];
    __syncthreads();

    const int ty = tid >> 4, tx = tid & 15;
    const int rb = ty * 4, cb = tx * 4;

    float a[4][4];
#pragma unroll
    for (int i = 0; i < 4; i++)
#pragma unroll
        for (int j = 0; j < 4; j++) a[i][j] = 0.f;

    for (int d = 0; d < 64; d++) {
        float4 q4 = *(float4*)&Qt[d * 68 + rb];
        float4 k4 = *(float4*)&Kt[d * 68 + cb];
        float qv[4] = {q4.x, q4.y, q4.z, q4.w};
        float kv[4] = {k4.x, k4.y, k4.z, k4.w};
#pragma unroll
        for (int i = 0; i < 4; i++)
#pragma unroll
            for (int j = 0; j < 4; j++)
                a[i][j] += qv[i] * kv[j];
    }
#pragma unroll
    for (int i = 0; i < 4; i++)
#pragma unroll
        for (int j = 0; j < 4; j++) {
            int ti = rb + i, tj = cb + j;
            At[tj * 68 + ti] = (tj <= ti) ? a[i][j] : 0.f;
        }
    __syncthreads();

    if (tid < 64) {
        float s = 0.f;
        for (int tj = 0; tj < 64; tj++) s += At[tj * 68 + tid];
        for (int d = 0; d < 64; d++) s += Qt[d * 68 + tid] * pks[d];
        dinv[tid] = 1.0f / fmaxf(s, 1e-6f);
    }
    __syncthreads();

    float o[4][4];
#pragma unroll
    for (int i = 0; i < 4; i++)
#pragma unroll
        for (int j = 0; j < 4; j++) o[i][j] = 0.f;

    for (int tj = 0; tj < 64; tj++) {
        float4 a4 = *(float4*)&At[tj * 68 + rb];
        float4 v4 = *(float4*)&Vs[tj * 64 + cb];
        float av[4] = {a4.x, a4.y, a4.z, a4.w};
        float vv[4] = {v4.x, v4.y, v4.z, v4.w};
#pragma unroll
        for (int i = 0; i < 4; i++)
#pragma unroll
            for (int j = 0; j < 4; j++)
                o[i][j] += av[i] * vv[j];
    }
    for (int d = 0; d < 64; d++) {
        float4 q4 = *(float4*)&Qt[d * 68 + rb];
        float4 p4 = *(float4*)&Ps[d * 64 + cb];
        float qv[4] = {q4.x, q4.y, q4.z, q4.w};
        float pv[4] = {p4.x, p4.y, p4.z, p4.w};
#pragma unroll
        for (int i = 0; i < 4; i++)
#pragma unroll
            for (int j = 0; j < 4; j++)
                o[i][j] += qv[i] * pv[j];
    }

    const int b = bh >> 4, h = bh & 15;
#pragma unroll
    for (int i = 0; i < 4; i++) {
        int ti = rb + i;
        float di = dinv[ti];
        __nv_bfloat16 hv[4], lv[4];
#pragma unroll
        for (int j = 0; j < 4; j++) {
            float v = o[i][j] * di;
            hv[j] = __float2bfloat16(v);
            lv[j] = __float2bfloat16(v - __bfloat162float(hv[j]));
        }
        size_t oidx = (size_t)(b * SEQ + t0 + ti) * DIM + h * 64 + cb;
        *(uint2*)(g_ahi + oidx) = *(uint2*)hv;
        *(uint2*)(g_alo + oidx) = *(uint2*)lv;
    }
}

// ================= launch =================
extern "C" void kernel_launch(void* const* d_in, const int* in_sizes, int n_in,
                              void* d_out, int out_size)
{
    const float* x     = (const float*)d_in[0];
    const float* w_qkv = (const float*)d_in[1];
    const float* w_out = (const float*)d_in[2];
    float* out = (float*)d_out;

    __nv_bfloat16 *xhi, *xlo, *wqhi, *wqlo, *wohi, *wolo, *ahi, *alo;
    cudaGetSymbolAddress((void**)&xhi,  g_xhi);
    cudaGetSymbolAddress((void**)&xlo,  g_xlo);
    cudaGetSymbolAddress((void**)&wqhi, g_wqhi);
    cudaGetSymbolAddress((void**)&wqlo, g_wqlo);
    cudaGetSymbolAddress((void**)&wohi, g_wohi);
    cudaGetSymbolAddress((void**)&wolo, g_wolo);
    cudaGetSymbolAddress((void**)&ahi,  g_ahi);
    cudaGetSymbolAddress((void**)&alo,  g_alo);

    cudaFuncSetAttribute(gemm_tc<0>, cudaFuncAttributeMaxDynamicSharedMemorySize, GEMM_SMEM);
    cudaFuncSetAttribute(gemm_tc<1>, cudaFuncAttributeMaxDynamicSharedMemorySize, GEMM_SMEM);
    const int attn_smem = (64 * 68 * 3 + 64 * 64 * 2 + 128) * 4;
    cudaFuncSetAttribute(attn_kernel, cudaFuncAttributeMaxDynamicSharedMemorySize, attn_smem);

    // 0) rope table + splits
    rope_init<<<(SEQ * 32) / 256, 256>>>();
    split_kernel<<<(MTOT * DIM) / (256 * 4), 256>>>(x, xhi, xlo);
    tsplit_kernel<<<dim3(3 * DIM / 32, DIM / 32), dim3(32, 8)>>>(w_qkv, wqhi, wqlo, DIM, 3 * DIM);
    tsplit_kernel<<<dim3(DIM / 32, DIM / 32), dim3(32, 8)>>>(w_out, wohi, wolo, DIM, DIM);

    // 1) QKV projection + fused RoPE/ELU featmap
    gemm_tc<1><<<dim3(3 * DIM / 128, MTOT / 128), 256, GEMM_SMEM>>>(xhi, xlo, wqhi, wqlo, nullptr, 3 * DIM);

    // 2) per-chunk K^T V and sum(k)
    chunksum_kernel<<<dim3(NCHUNK, BH), 256>>>();

    // 3) merged exclusive prefixes
    prefix_kernel<<<1024 + 16, 256>>>();

    // 4) chunk attention -> bf16 hi/lo activations
    attn_kernel<<<dim3(NCHUNK, BH), 256, attn_smem>>>();

    // 5) output projection
    gemm_tc<0><<<dim3(DIM / 128, MTOT / 128), 256, GEMM_SMEM>>>(ahi, alo, wohi, wolo, out, DIM);
}